// round 1
// baseline (speedup 1.0000x reference)
#include <cuda_runtime.h>
#include <cuda_bf16.h>

// Problem constants (fixed by dataset)
#define MAXN 50000
#define CDIM 64
#define SDIM 4
#define ODIM 64
#define KNEI 16

// Scratch tables (static __device__ — allocation-free per harness rules)
__device__ float g_v[MAXN * SDIM * ODIM];   // 51.2 MB: (src[j]@W_lin[s] + b_lin[s]) / 4
__device__ float g_t[MAXN * SDIM];          // x[n]@Wt + bt
__device__ float g_sl[MAXN * SDIM];         // src[j]@Ws + bs

// ---------------------------------------------------------------------------
// Kernel 1: per-row logits. One warp per node; lanes cover 2 channels each.
// ---------------------------------------------------------------------------
__global__ void k_logits(const float* __restrict__ x,
                         const float* __restrict__ src,
                         const float* __restrict__ Wt,  // [64,4]
                         const float* __restrict__ bt,  // [4]
                         const float* __restrict__ Ws,  // [64,4]
                         const float* __restrict__ bs,  // [4]
                         int N)
{
    int warp = (blockIdx.x * blockDim.x + threadIdx.x) >> 5;
    int lane = threadIdx.x & 31;
    if (warp >= N) return;

    float pt[4] = {0.f, 0.f, 0.f, 0.f};
    float ps[4] = {0.f, 0.f, 0.f, 0.f};

#pragma unroll
    for (int h = 0; h < 2; h++) {
        int c = lane + 32 * h;
        float xc = __ldg(x + warp * CDIM + c);
        float sc = __ldg(src + warp * CDIM + c);
        float4 wt = __ldg((const float4*)Wt + c);
        float4 ws = __ldg((const float4*)Ws + c);
        pt[0] += xc * wt.x; pt[1] += xc * wt.y; pt[2] += xc * wt.z; pt[3] += xc * wt.w;
        ps[0] += sc * ws.x; ps[1] += sc * ws.y; ps[2] += sc * ws.z; ps[3] += sc * ws.w;
    }

#pragma unroll
    for (int off = 16; off; off >>= 1) {
#pragma unroll
        for (int i = 0; i < 4; i++) {
            pt[i] += __shfl_xor_sync(0xFFFFFFFFu, pt[i], off);
            ps[i] += __shfl_xor_sync(0xFFFFFFFFu, ps[i], off);
        }
    }

    if (lane == 0) {
        float4 bt4 = __ldg((const float4*)bt);
        float4 bs4 = __ldg((const float4*)bs);
        float4 tv = make_float4(pt[0] + bt4.x, pt[1] + bt4.y, pt[2] + bt4.z, pt[3] + bt4.w);
        float4 sv = make_float4(ps[0] + bs4.x, ps[1] + bs4.y, ps[2] + bs4.z, ps[3] + bs4.w);
        ((float4*)g_t)[warp]  = tv;
        ((float4*)g_sl)[warp] = sv;
    }
}

// ---------------------------------------------------------------------------
// Kernel 2: v-table GEMM  C[N,256] = src[N,64] @ Wbig[64,256] (+b)/4
// 256 threads/block: thread 'so' owns output column so = s*64+o, holds the
// 64-entry W column in registers. src row read via warp-uniform LDG broadcast.
// ---------------------------------------------------------------------------
__global__ void __launch_bounds__(256) k_vtable(const float* __restrict__ src,
                                                const float* __restrict__ W_lin,  // [4,64,64]
                                                const float* __restrict__ b_lin,  // [4,64]
                                                int N)
{
    int so = threadIdx.x;          // 0..255
    int s = so >> 6;
    int o = so & 63;

    float w[CDIM];
#pragma unroll
    for (int c = 0; c < CDIM; c++)
        w[c] = __ldg(W_lin + s * (CDIM * ODIM) + c * ODIM + o);   // W_lin[s][c][o]

    float b = __ldg(b_lin + so) * 0.25f;

    for (int j = blockIdx.x; j < N; j += gridDim.x) {
        const float4* sr = (const float4*)(src + j * CDIM);
        float acc = 0.f;
#pragma unroll
        for (int i = 0; i < CDIM / 4; i++) {
            float4 sv = __ldg(sr + i);   // warp-uniform broadcast
            acc += sv.x * w[4 * i + 0];
            acc += sv.y * w[4 * i + 1];
            acc += sv.z * w[4 * i + 2];
            acc += sv.w * w[4 * i + 3];
        }
        g_v[j * (SDIM * ODIM) + so] = fmaf(acc, 0.25f, b);
    }
}

// ---------------------------------------------------------------------------
// Kernel 3: gather + softmax(4) + weighted combine. One warp per (n,k).
// Lane l covers outputs {2l, 2l+1} via float2; all v/out accesses coalesced.
// ---------------------------------------------------------------------------
__global__ void __launch_bounds__(256) k_gather(const int* __restrict__ idx,
                                                float* __restrict__ out,
                                                int total /* N*K */)
{
    int w = (blockIdx.x * blockDim.x + threadIdx.x) >> 5;
    int lane = threadIdx.x & 31;
    if (w >= total) return;

    int n = w >> 4;                 // K = 16
    int j = __ldg(idx + w);

    float4 tv = __ldg((const float4*)g_t + n);
    float4 sv = __ldg((const float4*)g_sl + j);

    float l0 = tv.x + sv.x, l1 = tv.y + sv.y, l2 = tv.z + sv.z, l3 = tv.w + sv.w;
    float m = fmaxf(fmaxf(l0, l1), fmaxf(l2, l3));
    float e0 = __expf(l0 - m), e1 = __expf(l1 - m), e2 = __expf(l2 - m), e3 = __expf(l3 - m);
    float inv = 1.0f / (e0 + e1 + e2 + e3);
    float a0 = e0 * inv, a1 = e1 * inv, a2 = e2 * inv, a3 = e3 * inv;

    const float2* vr = (const float2*)(g_v + j * (SDIM * ODIM)) + lane;
    float2 v0 = __ldg(vr);
    float2 v1 = __ldg(vr + 32);
    float2 v2 = __ldg(vr + 64);
    float2 v3 = __ldg(vr + 96);

    float2 r;
    r.x = a0 * v0.x + a1 * v1.x + a2 * v2.x + a3 * v3.x;
    r.y = a0 * v0.y + a1 * v1.y + a2 * v2.y + a3 * v3.y;

    ((float2*)out)[w * 32 + lane] = r;
}

// ---------------------------------------------------------------------------
extern "C" void kernel_launch(void* const* d_in, const int* in_sizes, int n_in,
                              void* d_out, int out_size)
{
    const float* x     = (const float*)d_in[0];
    const float* src   = (const float*)d_in[1];
    const int*   nidx  = (const int*)d_in[2];
    const float* Wt    = (const float*)d_in[3];
    const float* bt    = (const float*)d_in[4];
    const float* Ws    = (const float*)d_in[5];
    const float* bs    = (const float*)d_in[6];
    const float* W_lin = (const float*)d_in[7];
    const float* b_lin = (const float*)d_in[8];
    float* out = (float*)d_out;

    int N  = in_sizes[0] / CDIM;       // 50000
    int NK = in_sizes[2];              // N*K = 800000
    if (N > MAXN) N = MAXN;

    // 1) logits tables: one warp per node
    k_logits<<<(N + 7) / 8, 256>>>(x, src, Wt, bt, Ws, bs, N);

    // 2) v table: grid-stride over source rows
    k_vtable<<<592, 256>>>(src, W_lin, b_lin, N);

    // 3) gather + softmax + combine: one warp per (n,k)
    k_gather<<<(NK + 7) / 8, 256>>>(nidx, out, NK);
}

// round 2
// speedup vs baseline: 1.1165x; 1.1165x over previous
#include <cuda_runtime.h>
#include <cuda_fp16.h>

// Problem constants (fixed by dataset)
#define MAXN 50000
#define CDIM 64
#define SDIM 4
#define ODIM 64
#define KNEI 16

// Scratch tables (static __device__ — allocation-free per harness rules)
// v-table in fp16: v[j, t] holds output pair (2t, 2t+1) of (src[j]@W_lin[s]+b_lin[s])/4
__device__ __half2 g_vh[MAXN * 128];        // 25.6 MB — fits in L2
__device__ float   g_t[MAXN * SDIM];        // x[n]@Wt + bt
__device__ float   g_sl[MAXN * SDIM];       // src[j]@Ws + bs

// ---------------------------------------------------------------------------
// Kernel 1: logits tables. Block = 256 threads handles 64 nodes via smem tiles.
// thread t -> (node = t>>2, s = t&3). Padded tiles (stride 65) kill conflicts.
// ---------------------------------------------------------------------------
__global__ void __launch_bounds__(256) k_logits(const float* __restrict__ x,
                                                const float* __restrict__ src,
                                                const float* __restrict__ Wt,  // [64,4]
                                                const float* __restrict__ bt,  // [4]
                                                const float* __restrict__ Ws,  // [64,4]
                                                const float* __restrict__ bs,  // [4]
                                                int N)
{
    __shared__ float xs[64][65];
    __shared__ float ss[64][65];
    __shared__ float wts[64][4];
    __shared__ float wss[64][4];

    int tid = threadIdx.x;
    int nb  = blockIdx.x * 64;

    // stage W matrices (256 floats each)
    wts[tid >> 2][tid & 3] = __ldg(Wt + tid);
    wss[tid >> 2][tid & 3] = __ldg(Ws + tid);

    // stage x / src tiles, coalesced float4
    for (int i = tid; i < 64 * 16; i += 256) {
        int row = i >> 4, c4 = i & 15;
        int node = nb + row;
        float4 xv = make_float4(0.f, 0.f, 0.f, 0.f);
        float4 sv = make_float4(0.f, 0.f, 0.f, 0.f);
        if (node < N) {
            xv = __ldg((const float4*)x + node * 16 + c4);
            sv = __ldg((const float4*)src + node * 16 + c4);
        }
        xs[row][c4 * 4 + 0] = xv.x; xs[row][c4 * 4 + 1] = xv.y;
        xs[row][c4 * 4 + 2] = xv.z; xs[row][c4 * 4 + 3] = xv.w;
        ss[row][c4 * 4 + 0] = sv.x; ss[row][c4 * 4 + 1] = sv.y;
        ss[row][c4 * 4 + 2] = sv.z; ss[row][c4 * 4 + 3] = sv.w;
    }
    __syncthreads();

    int node = tid >> 2;
    int s    = tid & 3;
    float at = __ldg(bt + s);
    float as_ = __ldg(bs + s);
#pragma unroll
    for (int c = 0; c < CDIM; c++) {
        at  = fmaf(xs[node][c], wts[c][s], at);
        as_ = fmaf(ss[node][c], wss[c][s], as_);
    }
    int gn = nb + node;
    if (gn < N) {
        g_t[gn * 4 + s]  = at;
        g_sl[gn * 4 + s] = as_;
    }
}

// ---------------------------------------------------------------------------
// Kernel 2: v-table GEMM via packed f32x2 FMA.
// 128 threads/block; thread t owns column pair (2t, 2t+1) of the 256 outputs
// (s = t>>5). W column pair held in registers as packed b64 (float2 loads).
// Per channel: 1 pack (ALU) + 1 fma.rn.f32x2 (FMA) -> 2x scalar-FFMA issue rate.
// ---------------------------------------------------------------------------
__global__ void __launch_bounds__(128) k_vtable(const float* __restrict__ src,
                                                const float* __restrict__ W_lin,  // [4,64,64]
                                                const float* __restrict__ b_lin,  // [4,64]
                                                int N)
{
    int t = threadIdx.x;       // 0..127
    int s = t >> 5;            // 0..3
    int o2 = t & 31;           // float2 column index within the 64-wide output

    // Load the two W columns, packed: w64[c] = (W[s][c][2*o2], W[s][c][2*o2+1])
    unsigned long long w64[CDIM];
#pragma unroll
    for (int c = 0; c < CDIM; c++) {
        float2 w = __ldg((const float2*)(W_lin + s * (CDIM * ODIM) + c * ODIM) + o2);
        w64[c] = *reinterpret_cast<unsigned long long*>(&w);
    }

    float2 b2 = __ldg((const float2*)(b_lin + s * ODIM) + o2);
    unsigned long long bias64 = *reinterpret_cast<unsigned long long*>(&b2);

    for (int j = blockIdx.x; j < N; j += gridDim.x) {
        const float4* sr = (const float4*)(src + j * CDIM);
        unsigned long long acc = bias64;
#pragma unroll
        for (int i = 0; i < CDIM / 4; i++) {
            float4 sv = __ldg(sr + i);   // warp-uniform broadcast
            unsigned long long p;
            asm("mov.b64 %0, {%1, %1};" : "=l"(p) : "r"(__float_as_uint(sv.x)));
            asm("fma.rn.f32x2 %0, %1, %2, %3;" : "=l"(acc) : "l"(w64[4*i+0]), "l"(p), "l"(acc));
            asm("mov.b64 %0, {%1, %1};" : "=l"(p) : "r"(__float_as_uint(sv.y)));
            asm("fma.rn.f32x2 %0, %1, %2, %3;" : "=l"(acc) : "l"(w64[4*i+1]), "l"(p), "l"(acc));
            asm("mov.b64 %0, {%1, %1};" : "=l"(p) : "r"(__float_as_uint(sv.z)));
            asm("fma.rn.f32x2 %0, %1, %2, %3;" : "=l"(acc) : "l"(w64[4*i+2]), "l"(p), "l"(acc));
            asm("mov.b64 %0, {%1, %1};" : "=l"(p) : "r"(__float_as_uint(sv.w)));
            asm("fma.rn.f32x2 %0, %1, %2, %3;" : "=l"(acc) : "l"(w64[4*i+3]), "l"(p), "l"(acc));
        }
        unsigned int lo, hi;
        asm("mov.b64 {%0, %1}, %2;" : "=r"(lo), "=r"(hi) : "l"(acc));
        float r0 = __uint_as_float(lo) * 0.25f;
        float r1 = __uint_as_float(hi) * 0.25f;
        g_vh[j * 128 + t] = __floats2half2_rn(r0, r1);
    }
}

// ---------------------------------------------------------------------------
// Kernel 3: gather + softmax(4) + weighted combine. One warp per (n,k).
// Lane l covers outputs {2l, 2l+1}; v-table reads are fp16 (half traffic),
// coalesced 128B per row per warp.
// ---------------------------------------------------------------------------
__global__ void __launch_bounds__(256) k_gather(const int* __restrict__ idx,
                                                float* __restrict__ out,
                                                int total /* N*K */)
{
    int w = (blockIdx.x * blockDim.x + threadIdx.x) >> 5;
    int lane = threadIdx.x & 31;
    if (w >= total) return;

    int n = w >> 4;                 // K = 16
    int j = __ldg(idx + w);

    float4 tv = __ldg((const float4*)g_t + n);
    float4 sv = __ldg((const float4*)g_sl + j);

    float l0 = tv.x + sv.x, l1 = tv.y + sv.y, l2 = tv.z + sv.z, l3 = tv.w + sv.w;
    float m = fmaxf(fmaxf(l0, l1), fmaxf(l2, l3));
    float e0 = __expf(l0 - m), e1 = __expf(l1 - m), e2 = __expf(l2 - m), e3 = __expf(l3 - m);
    float inv = 1.0f / (e0 + e1 + e2 + e3);
    float a0 = e0 * inv, a1 = e1 * inv, a2 = e2 * inv, a3 = e3 * inv;

    const __half2* vr = g_vh + j * 128 + lane;
    float2 f0 = __half22float2(__ldg(vr));
    float2 f1 = __half22float2(__ldg(vr + 32));
    float2 f2 = __half22float2(__ldg(vr + 64));
    float2 f3 = __half22float2(__ldg(vr + 96));

    float2 r;
    r.x = a0 * f0.x + a1 * f1.x + a2 * f2.x + a3 * f3.x;
    r.y = a0 * f0.y + a1 * f1.y + a2 * f2.y + a3 * f3.y;

    ((float2*)out)[w * 32 + lane] = r;
}

// ---------------------------------------------------------------------------
extern "C" void kernel_launch(void* const* d_in, const int* in_sizes, int n_in,
                              void* d_out, int out_size)
{
    const float* x     = (const float*)d_in[0];
    const float* src   = (const float*)d_in[1];
    const int*   nidx  = (const int*)d_in[2];
    const float* Wt    = (const float*)d_in[3];
    const float* bt    = (const float*)d_in[4];
    const float* Ws    = (const float*)d_in[5];
    const float* bs    = (const float*)d_in[6];
    const float* W_lin = (const float*)d_in[7];
    const float* b_lin = (const float*)d_in[8];
    float* out = (float*)d_out;

    int N  = in_sizes[0] / CDIM;       // 50000
    int NK = in_sizes[2];              // N*K = 800000
    if (N > MAXN) N = MAXN;

    // 1) logits tables: 64 nodes per block
    k_logits<<<(N + 63) / 64, 256>>>(x, src, Wt, bt, Ws, bs, N);

    // 2) v table (fp16): grid-stride over source rows
    k_vtable<<<1184, 128>>>(src, W_lin, b_lin, N);

    // 3) gather + softmax + combine: one warp per (n,k)
    k_gather<<<(NK + 7) / 8, 256>>>(nidx, out, NK);
}